// round 11
// baseline (speedup 1.0000x reference)
#include <cuda_runtime.h>
#include <cuda_fp16.h>
#include <cstdint>

// ===========================================================================
// GGUFWeight (sm_103 portable path): out = x @ W^T + bias, W = scale*(q-8).
// M=8192, N=4096, K=4096.
// Phase 1 (one kernel): x -> fp16 g_X, dequant W -> fp16 g_W.
// Phase 2: mma.sync.m16n8k16 GEMM, 256x128 CTA tile, BK=64, 4-stage cp.async,
//          256 threads (8 warps, 4(M)x2(N) grid, 64x64 warp tile),
//          double-buffered ldmatrix fragments, fp32 accum, fused bias.
// ===========================================================================

#define THREADS 256
#define BM 256
#define BN 128
#define BK 64
#define STAGES 4
#define A_STAGE_BYTES (BM * 128)             // 256 rows * 128B = 32768
#define B_STAGE_BYTES (BN * 128)             // 128 rows * 128B = 16384
#define STAGE_BYTES (A_STAGE_BYTES + B_STAGE_BYTES)   // 49152
#define SMEM_TOTAL (STAGES * STAGE_BYTES)             // 196608

__device__ __half g_X[8192ull * 4096ull];   // [M,K] K-major fp16
__device__ __half g_W[4096ull * 4096ull];   // [N,K] K-major fp16

// ---------------------------------------------------------------------------
__device__ __forceinline__ uint32_t smem_u32(const void* p) {
    uint32_t a;
    asm("{ .reg .u64 t; cvta.to.shared.u64 t, %1; cvt.u32.u64 %0, t; }"
        : "=r"(a) : "l"(p));
    return a;
}

#define CP_ASYNC16(dst, src) \
    asm volatile("cp.async.cg.shared.global [%0], [%1], 16;" \
                 :: "r"(dst), "l"(src) : "memory")
#define CP_COMMIT() asm volatile("cp.async.commit_group;" ::: "memory")
#define CP_WAIT(n)  asm volatile("cp.async.wait_group %0;" :: "n"(n) : "memory")

#define LDSM_X4(r0, r1, r2, r3, addr) \
    asm volatile("ldmatrix.sync.aligned.m8n8.x4.shared.b16 {%0,%1,%2,%3}, [%4];" \
                 : "=r"(r0), "=r"(r1), "=r"(r2), "=r"(r3) : "r"(addr))

#define MMA16816(c0, c1, c2, c3, a0, a1, a2, a3, b0, b1) \
    asm volatile("mma.sync.aligned.m16n8k16.row.col.f32.f16.f16.f32 " \
                 "{%0,%1,%2,%3}, {%4,%5,%6,%7}, {%8,%9}, {%0,%1,%2,%3};" \
                 : "+f"(c0), "+f"(c1), "+f"(c2), "+f"(c3) \
                 : "r"(a0), "r"(a1), "r"(a2), "r"(a3), "r"(b0), "r"(b1))

// ---------------------------------------------------------------------------
// Fused conversion kernel
// ---------------------------------------------------------------------------
__global__ void convert_all_kernel(const float* __restrict__ x,
                                   const int* __restrict__ q,
                                   const float* __restrict__ scales,
                                   int K, unsigned xBlocks) {
    if (blockIdx.x < xBlocks) {
        size_t i = ((size_t)blockIdx.x * blockDim.x + threadIdx.x) * 8;
        float4 a = *reinterpret_cast<const float4*>(x + i);
        float4 b = *reinterpret_cast<const float4*>(x + i + 4);
        __half h[8];
        h[0] = __float2half_rn(a.x); h[1] = __float2half_rn(a.y);
        h[2] = __float2half_rn(a.z); h[3] = __float2half_rn(a.w);
        h[4] = __float2half_rn(b.x); h[5] = __float2half_rn(b.y);
        h[6] = __float2half_rn(b.z); h[7] = __float2half_rn(b.w);
        *reinterpret_cast<uint4*>(g_X + i) = *reinterpret_cast<uint4*>(h);
    } else {
        size_t i = ((size_t)(blockIdx.x - xBlocks) * blockDim.x + threadIdx.x) * 8;
        int4 q0 = *reinterpret_cast<const int4*>(q + i);
        int4 q1 = *reinterpret_cast<const int4*>(q + i + 4);
        int k = (int)(i % (size_t)K);
        int n = (int)(i / (size_t)K);
        float s = scales[(size_t)n * (K >> 5) + (k >> 5)];
        __half h[8];
        h[0] = __float2half_rn(s * (float)(q0.x - 8));
        h[1] = __float2half_rn(s * (float)(q0.y - 8));
        h[2] = __float2half_rn(s * (float)(q0.z - 8));
        h[3] = __float2half_rn(s * (float)(q0.w - 8));
        h[4] = __float2half_rn(s * (float)(q1.x - 8));
        h[5] = __float2half_rn(s * (float)(q1.y - 8));
        h[6] = __float2half_rn(s * (float)(q1.z - 8));
        h[7] = __float2half_rn(s * (float)(q1.w - 8));
        *reinterpret_cast<uint4*>(g_W + i) = *reinterpret_cast<uint4*>(h);
    }
}

// ---------------------------------------------------------------------------
// HMMA GEMM: 8 warps, warp grid 4(M) x 2(N), warp tile 64x64.
// Smem rows 128B (BK=64); chunk swizzle: stored_chunk = chunk ^ (row & 7).
// Fragments double-buffered across the 4 ks steps (k16 each).
// ---------------------------------------------------------------------------
__global__ void __launch_bounds__(THREADS, 1)
gemm_hmma_kernel(const float* __restrict__ bias, float* __restrict__ C,
                 int M, int N, int K) {
    extern __shared__ char smem[];
    const uint32_t smem_base = smem_u32(smem);
    const int tid = threadIdx.x;
    const int wid = tid >> 5;
    const int lane = tid & 31;

    const int bm = blockIdx.y * BM;
    const int bn = blockIdx.x * BN;

    const int warp_m = wid & 3;     // 4 warps over M (64 rows each)
    const int warp_n = wid >> 2;    // 2 warps over N (64 cols each)

    const __half* gA = g_X + (size_t)bm * K;
    const __half* gB = g_W + (size_t)bn * K;

    // Stage loader: A = 2048 16B-chunks (8/thread), B = 1024 (4/thread).
    auto load_stage = [&](int s, int kc) {
        const uint32_t sA = smem_base + s * STAGE_BYTES;
        const uint32_t sB = sA + A_STAGE_BYTES;
        const __half* gAk = gA + kc * BK;
        const __half* gBk = gB + kc * BK;
#pragma unroll
        for (int i = 0; i < 8; i++) {
            int cid = tid + (i << 8);          // 0..2047
            int row = cid >> 3, c = cid & 7;
            int sc = c ^ (row & 7);
            CP_ASYNC16(sA + row * 128 + (sc << 4),
                       gAk + (size_t)row * K + c * 8);
        }
#pragma unroll
        for (int i = 0; i < 4; i++) {
            int cid = tid + (i << 8);          // 0..1023
            int row = cid >> 3, c = cid & 7;
            int sc = c ^ (row & 7);
            CP_ASYNC16(sB + row * 128 + (sc << 4),
                       gBk + (size_t)row * K + c * 8);
        }
        CP_COMMIT();
    };

    // ldmatrix lane mapping (validated in prior rounds):
    // lanes 0-15 -> rows 0-15, lanes 16-31 -> adjacent 16B k-chunk.
    const int rowoff = lane & 15;
    const int csel   = (lane >> 4) & 1;
    const int swz    = rowoff & 7;

    const uint32_t aRowByte = (uint32_t)(warp_m * 64 + rowoff) * 128;
    const uint32_t bRowByte = (uint32_t)(warp_n * 64 + rowoff) * 128;

    float acc[4][8][4];
#pragma unroll
    for (int mt = 0; mt < 4; mt++)
#pragma unroll
        for (int j = 0; j < 8; j++)
#pragma unroll
            for (int r = 0; r < 4; r++) acc[mt][j][r] = 0.0f;

    const int nK = K / BK;   // 64 chunks

#pragma unroll
    for (int s = 0; s < STAGES - 1; s++) load_stage(s, s);

    // Double-buffered fragments
    uint32_t afr[2][4][4];   // [buf][mt][reg]
    uint32_t bfr[2][4][4];   // [buf][nt][reg]

    int s = 0;
    for (int kc = 0; kc < nK; kc++) {
        CP_WAIT(STAGES - 2);
        // Top barrier publishes stage kc AND protects stage (kc-1) from the
        // overwrite issued below (all its reads preceded this barrier).
        __syncthreads();

        if (kc + STAGES - 1 < nK)
            load_stage((kc + STAGES - 1) & (STAGES - 1), kc + STAGES - 1);

        const uint32_t sA = smem_base + s * STAGE_BYTES;
        const uint32_t sB = sA + A_STAGE_BYTES;

        // Preload ks=0 fragments into buffer 0
        {
            const int koff = ((csel) ^ swz) << 4;   // ks=0
#pragma unroll
            for (int mt = 0; mt < 4; mt++)
                LDSM_X4(afr[0][mt][0], afr[0][mt][1], afr[0][mt][2], afr[0][mt][3],
                        sA + aRowByte + mt * 2048 + koff);
#pragma unroll
            for (int nt = 0; nt < 4; nt++)
                LDSM_X4(bfr[0][nt][0], bfr[0][nt][1], bfr[0][nt][2], bfr[0][nt][3],
                        sB + bRowByte + nt * 2048 + koff);
        }

#pragma unroll
        for (int ks = 0; ks < 4; ks++) {
            const int cur = ks & 1;
            if (ks < 3) {
                const int nxt = cur ^ 1;
                const int koff = ((((ks + 1) << 1) + csel) ^ swz) << 4;
#pragma unroll
                for (int mt = 0; mt < 4; mt++)
                    LDSM_X4(afr[nxt][mt][0], afr[nxt][mt][1],
                            afr[nxt][mt][2], afr[nxt][mt][3],
                            sA + aRowByte + mt * 2048 + koff);
#pragma unroll
                for (int nt = 0; nt < 4; nt++)
                    LDSM_X4(bfr[nxt][nt][0], bfr[nxt][nt][1],
                            bfr[nxt][nt][2], bfr[nxt][nt][3],
                            sB + bRowByte + nt * 2048 + koff);
            }
#pragma unroll
            for (int mt = 0; mt < 4; mt++)
#pragma unroll
                for (int j = 0; j < 8; j++) {
                    const int nt = j >> 1, odd = j & 1;
                    MMA16816(acc[mt][j][0], acc[mt][j][1],
                             acc[mt][j][2], acc[mt][j][3],
                             afr[cur][mt][0], afr[cur][mt][1],
                             afr[cur][mt][2], afr[cur][mt][3],
                             bfr[cur][nt][odd], bfr[cur][nt][2 + odd]);
                }
        }
        s = (s + 1) & (STAGES - 1);
    }

    // Epilogue: fused bias, float2 stores.
    const int colb = bn + warp_n * 64 + (lane & 3) * 2;
    float2 brow[8];
#pragma unroll
    for (int j = 0; j < 8; j++)
        brow[j] = *reinterpret_cast<const float2*>(bias + colb + j * 8);

#pragma unroll
    for (int mt = 0; mt < 4; mt++) {
        const int row0 = bm + warp_m * 64 + mt * 16 + (lane >> 2);
#pragma unroll
        for (int j = 0; j < 8; j++) {
            const int col = colb + j * 8;
            float2 v0, v1;
            v0.x = acc[mt][j][0] + brow[j].x;
            v0.y = acc[mt][j][1] + brow[j].y;
            v1.x = acc[mt][j][2] + brow[j].x;
            v1.y = acc[mt][j][3] + brow[j].y;
            *reinterpret_cast<float2*>(C + (size_t)row0 * N + col) = v0;
            *reinterpret_cast<float2*>(C + (size_t)(row0 + 8) * N + col) = v1;
        }
    }
}

// ---------------------------------------------------------------------------
extern "C" void kernel_launch(void* const* d_in, const int* in_sizes, int n_in,
                              void* d_out, int out_size) {
    const float* x      = (const float*)d_in[0];
    const int*   qw     = (const int*)d_in[1];
    const float* scales = (const float*)d_in[2];
    const float* bias   = (const float*)d_in[3];
    float*       out    = (float*)d_out;

    const int N = in_sizes[3];           // 4096
    const int K = in_sizes[1] / N;       // 4096
    const int M = in_sizes[0] / K;       // 8192

    size_t xTotal = (size_t)M * K;
    size_t wTotal = (size_t)N * K;
    unsigned xBlocks = (unsigned)(xTotal / 8 / 256);   // 16384
    unsigned wBlocks = (unsigned)(wTotal / 8 / 256);   // 8192
    convert_all_kernel<<<xBlocks + wBlocks, 256>>>(x, qw, scales, K, xBlocks);

    cudaFuncSetAttribute(gemm_hmma_kernel,
                         cudaFuncAttributeMaxDynamicSharedMemorySize, SMEM_TOTAL);

    dim3 grid(N / BN, M / BM);     // (32, 32)
    gemm_hmma_kernel<<<grid, THREADS, SMEM_TOTAL>>>(bias, out, M, N, K);
}

// round 13
// speedup vs baseline: 1.0935x; 1.0935x over previous
#include <cuda_runtime.h>
#include <cuda_fp16.h>
#include <cstdint>

// ===========================================================================
// GGUFWeight (sm_103 portable path): out = x @ W^T + bias, W = scale*(q-8).
// M=8192, N=4096, K=4096.
// Phase 1 (one kernel): x -> fp16 g_X, dequant W -> fp16 g_W.
// Phase 2: mma.sync.m16n8k16 GEMM, 128x256 CTA tile, BK=128 (256B rows),
//          2-stage cp.async double buffer, 512 threads (16 warps, 4x4 grid,
//          32x64 warp tile), XOR swizzle per 128B half, fp32 accum, bias.
// ===========================================================================

#define THREADS 512
#define BM 128
#define BN 256
#define BK 128
#define STAGES 2
#define ROW_BYTES 256                         // BK=128 halves * 2B
#define A_STAGE_BYTES (BM * ROW_BYTES)        // 32768
#define B_STAGE_BYTES (BN * ROW_BYTES)        // 65536
#define STAGE_BYTES (A_STAGE_BYTES + B_STAGE_BYTES)   // 98304
#define SMEM_TOTAL (STAGES * STAGE_BYTES)             // 196608

__device__ __half g_X[8192ull * 4096ull];   // [M,K] K-major fp16
__device__ __half g_W[4096ull * 4096ull];   // [N,K] K-major fp16

// ---------------------------------------------------------------------------
__device__ __forceinline__ uint32_t smem_u32(const void* p) {
    uint32_t a;
    asm("{ .reg .u64 t; cvta.to.shared.u64 t, %1; cvt.u32.u64 %0, t; }"
        : "=r"(a) : "l"(p));
    return a;
}

#define CP_ASYNC16(dst, src) \
    asm volatile("cp.async.cg.shared.global [%0], [%1], 16;" \
                 :: "r"(dst), "l"(src) : "memory")
#define CP_COMMIT() asm volatile("cp.async.commit_group;" ::: "memory")
#define CP_WAIT(n)  asm volatile("cp.async.wait_group %0;" :: "n"(n) : "memory")

#define LDSM_X4(r0, r1, r2, r3, addr) \
    asm volatile("ldmatrix.sync.aligned.m8n8.x4.shared.b16 {%0,%1,%2,%3}, [%4];" \
                 : "=r"(r0), "=r"(r1), "=r"(r2), "=r"(r3) : "r"(addr))

#define MMA16816(c0, c1, c2, c3, a0, a1, a2, a3, b0, b1) \
    asm volatile("mma.sync.aligned.m16n8k16.row.col.f32.f16.f16.f32 " \
                 "{%0,%1,%2,%3}, {%4,%5,%6,%7}, {%8,%9}, {%0,%1,%2,%3};" \
                 : "+f"(c0), "+f"(c1), "+f"(c2), "+f"(c3) \
                 : "r"(a0), "r"(a1), "r"(a2), "r"(a3), "r"(b0), "r"(b1))

// ---------------------------------------------------------------------------
// Fused conversion kernel
// ---------------------------------------------------------------------------
__global__ void convert_all_kernel(const float* __restrict__ x,
                                   const int* __restrict__ q,
                                   const float* __restrict__ scales,
                                   int K, unsigned xBlocks) {
    if (blockIdx.x < xBlocks) {
        size_t i = ((size_t)blockIdx.x * blockDim.x + threadIdx.x) * 8;
        float4 a = *reinterpret_cast<const float4*>(x + i);
        float4 b = *reinterpret_cast<const float4*>(x + i + 4);
        __half h[8];
        h[0] = __float2half_rn(a.x); h[1] = __float2half_rn(a.y);
        h[2] = __float2half_rn(a.z); h[3] = __float2half_rn(a.w);
        h[4] = __float2half_rn(b.x); h[5] = __float2half_rn(b.y);
        h[6] = __float2half_rn(b.z); h[7] = __float2half_rn(b.w);
        *reinterpret_cast<uint4*>(g_X + i) = *reinterpret_cast<uint4*>(h);
    } else {
        size_t i = ((size_t)(blockIdx.x - xBlocks) * blockDim.x + threadIdx.x) * 8;
        int4 q0 = *reinterpret_cast<const int4*>(q + i);
        int4 q1 = *reinterpret_cast<const int4*>(q + i + 4);
        int k = (int)(i % (size_t)K);
        int n = (int)(i / (size_t)K);
        float s = scales[(size_t)n * (K >> 5) + (k >> 5)];
        __half h[8];
        h[0] = __float2half_rn(s * (float)(q0.x - 8));
        h[1] = __float2half_rn(s * (float)(q0.y - 8));
        h[2] = __float2half_rn(s * (float)(q0.z - 8));
        h[3] = __float2half_rn(s * (float)(q0.w - 8));
        h[4] = __float2half_rn(s * (float)(q1.x - 8));
        h[5] = __float2half_rn(s * (float)(q1.y - 8));
        h[6] = __float2half_rn(s * (float)(q1.z - 8));
        h[7] = __float2half_rn(s * (float)(q1.w - 8));
        *reinterpret_cast<uint4*>(g_W + i) = *reinterpret_cast<uint4*>(h);
    }
}

// ---------------------------------------------------------------------------
// HMMA GEMM: 16 warps, warp grid 4(M) x 4(N), warp tile 32x64.
// Smem rows 256B (BK=128 halves); XOR swizzle applied within each 128B half:
//   stored_chunk = (c & 8) | ((c & 7) ^ (row & 7)),  c in [0,16) 16B chunks.
// ---------------------------------------------------------------------------
__global__ void __launch_bounds__(THREADS, 1)
gemm_hmma_kernel(const float* __restrict__ bias, float* __restrict__ C,
                 int M, int N, int K) {
    extern __shared__ char smem[];
    const uint32_t smem_base = smem_u32(smem);
    const int tid = threadIdx.x;
    const int wid = tid >> 5;
    const int lane = tid & 31;

    const int bm = blockIdx.y * BM;
    const int bn = blockIdx.x * BN;

    const int warp_m = wid & 3;     // 4 warps over M (32 rows each)
    const int warp_n = wid >> 2;    // 4 warps over N (64 cols each)

    const __half* gA = g_X + (size_t)bm * K;
    const __half* gB = g_W + (size_t)bn * K;

    // Stage loader: A = 2048 16B-chunks (4/thread), B = 4096 (8/thread).
    auto load_stage = [&](int s, int kc) {
        const uint32_t sA = smem_base + s * STAGE_BYTES;
        const uint32_t sB = sA + A_STAGE_BYTES;
        const __half* gAk = gA + kc * BK;
        const __half* gBk = gB + kc * BK;
#pragma unroll
        for (int i = 0; i < 4; i++) {
            int cid = tid + (i << 9);          // 0..2047
            int row = cid >> 4, c = cid & 15;
            int sc = (c & 8) | ((c & 7) ^ (row & 7));
            CP_ASYNC16(sA + row * ROW_BYTES + (sc << 4),
                       gAk + (size_t)row * K + c * 8);
        }
#pragma unroll
        for (int i = 0; i < 8; i++) {
            int cid = tid + (i << 9);          // 0..4095
            int row = cid >> 4, c = cid & 15;
            int sc = (c & 8) | ((c & 7) ^ (row & 7));
            CP_ASYNC16(sB + row * ROW_BYTES + (sc << 4),
                       gBk + (size_t)row * K + c * 8);
        }
        CP_COMMIT();
    };

    // ldmatrix lane mapping: lanes 0-15 -> rows, lanes 16-31 -> adjacent chunk.
    const int rowoff = lane & 15;
    const int csel   = (lane >> 4) & 1;
    const int swz    = rowoff & 7;

    const uint32_t aRowByte = (uint32_t)(warp_m * 32 + rowoff) * ROW_BYTES;
    const uint32_t bRowByte = (uint32_t)(warp_n * 64 + rowoff) * ROW_BYTES;

    float acc[2][8][4];
#pragma unroll
    for (int mt = 0; mt < 2; mt++)
#pragma unroll
        for (int j = 0; j < 8; j++)
#pragma unroll
            for (int r = 0; r < 4; r++) acc[mt][j][r] = 0.0f;

    const int nK = K / BK;   // 32 chunks

    load_stage(0, 0);        // STAGES-1 = 1 prefetch

    int s = 0;
    for (int kc = 0; kc < nK; kc++) {
        CP_WAIT(0);
        // Publishes stage kc to all warps; also orders all reads of the other
        // buffer (done in iteration kc-1) before its overwrite below.
        __syncthreads();

        if (kc + 1 < nK) load_stage(s ^ 1, kc + 1);

        const uint32_t sA = smem_base + s * STAGE_BYTES;
        const uint32_t sB = sA + A_STAGE_BYTES;

#pragma unroll
        for (int ks = 0; ks < 8; ks++) {
            const int chunk = (ks << 1) + csel;                    // 0..15
            const int koff = (((chunk & 8) | ((chunk & 7) ^ swz)) << 4);
            uint32_t a[2][4];
#pragma unroll
            for (int mt = 0; mt < 2; mt++)
                LDSM_X4(a[mt][0], a[mt][1], a[mt][2], a[mt][3],
                        sA + aRowByte + mt * (16 * ROW_BYTES) + koff);
            uint32_t b[4][4];
#pragma unroll
            for (int nt = 0; nt < 4; nt++)
                LDSM_X4(b[nt][0], b[nt][1], b[nt][2], b[nt][3],
                        sB + bRowByte + nt * (16 * ROW_BYTES) + koff);
#pragma unroll
            for (int mt = 0; mt < 2; mt++)
#pragma unroll
                for (int j = 0; j < 8; j++) {
                    const int nt = j >> 1, odd = j & 1;
                    MMA16816(acc[mt][j][0], acc[mt][j][1],
                             acc[mt][j][2], acc[mt][j][3],
                             a[mt][0], a[mt][1], a[mt][2], a[mt][3],
                             b[nt][odd], b[nt][2 + odd]);
                }
        }
        s ^= 1;
    }

    // Epilogue: fused bias, float2 stores.
    const int colb = bn + warp_n * 64 + (lane & 3) * 2;
    float2 brow[8];
#pragma unroll
    for (int j = 0; j < 8; j++)
        brow[j] = *reinterpret_cast<const float2*>(bias + colb + j * 8);

#pragma unroll
    for (int mt = 0; mt < 2; mt++) {
        const int row0 = bm + warp_m * 32 + mt * 16 + (lane >> 2);
#pragma unroll
        for (int j = 0; j < 8; j++) {
            const int col = colb + j * 8;
            float2 v0, v1;
            v0.x = acc[mt][j][0] + brow[j].x;
            v0.y = acc[mt][j][1] + brow[j].y;
            v1.x = acc[mt][j][2] + brow[j].x;
            v1.y = acc[mt][j][3] + brow[j].y;
            *reinterpret_cast<float2*>(C + (size_t)row0 * N + col) = v0;
            *reinterpret_cast<float2*>(C + (size_t)(row0 + 8) * N + col) = v1;
        }
    }
}

// ---------------------------------------------------------------------------
extern "C" void kernel_launch(void* const* d_in, const int* in_sizes, int n_in,
                              void* d_out, int out_size) {
    const float* x      = (const float*)d_in[0];
    const int*   qw     = (const int*)d_in[1];
    const float* scales = (const float*)d_in[2];
    const float* bias   = (const float*)d_in[3];
    float*       out    = (float*)d_out;

    const int N = in_sizes[3];           // 4096
    const int K = in_sizes[1] / N;       // 4096
    const int M = in_sizes[0] / K;       // 8192

    size_t xTotal = (size_t)M * K;
    size_t wTotal = (size_t)N * K;
    unsigned xBlocks = (unsigned)(xTotal / 8 / 256);   // 16384
    unsigned wBlocks = (unsigned)(wTotal / 8 / 256);   // 8192
    convert_all_kernel<<<xBlocks + wBlocks, 256>>>(x, qw, scales, K, xBlocks);

    cudaFuncSetAttribute(gemm_hmma_kernel,
                         cudaFuncAttributeMaxDynamicSharedMemorySize, SMEM_TOTAL);

    dim3 grid(N / BN, M / BM);     // (16, 64)
    gemm_hmma_kernel<<<grid, THREADS, SMEM_TOTAL>>>(bias, out, M, N, K);
}